// round 13
// baseline (speedup 1.0000x reference)
#include <cuda_runtime.h>
#include <cuda_fp16.h>
#include <math.h>
#include <stdint.h>

#define NROWS 4096
#define TWO_N 8192
#define D 128
#define NJOBS 1056                  // sum_I (32 - I/2), I=0..63
#define GRID_MAIN 148
#define PSC 3.798282565009841f      // sqrt(10/ln2) pre-scale
#define NEG_C2 0xCB37CB37u          // packed f16x2 (-C,-C), C = 14.4296875 (f16-exact)
#define TAIL_C 10.00189733f         // C * ln(2)
#define DIAG_F 0.99810459f          // exact diag term e^(10 - TAIL_C)

// ---------------- device scratch (allocation-free) ----------------
__device__ __half         g_h[(TWO_N + 128) * D];      // +128 zero phantom rows
__device__ float          g_pos[TWO_N];
__device__ float          g_part[(TWO_N + 128) * 128]; // [row][slot]; slot<32 row-parts(k), 32+I col-parts
__device__ float          g_bsum[32];
__device__ unsigned int   g_cnt;

// ---------------- smem map (dynamic) ----------------
#define SM_A      0
#define SM_B(s)   (32768 + (s) * 65536)        // 64KB stages (256 rows x 256B)
#define SM_RED(b) (163840 + (b) * 4096)        // rowred[128][4] then colred[256][2]
#define SMEM_BYTES 172032

// ---------------- helpers ----------------
__device__ __forceinline__ uint32_t smem_u32(const void* p) {
    uint32_t a;
    asm("{ .reg .u64 t; cvta.to.shared.u64 t, %1; cvt.u32.u64 %0, t; }" : "=r"(a) : "l"(p));
    return a;
}
__device__ __forceinline__ void ex2_h2_ip(uint32_t& x) {
    asm volatile("ex2.approx.f16x2 %0, %0;" : "+r"(x));
}
__device__ __forceinline__ uint32_t hadd2(uint32_t a, uint32_t b) {
    uint32_t r; asm("add.rn.f16x2 %0, %1, %2;" : "=r"(r) : "r"(a), "r"(b)); return r;
}
__device__ __forceinline__ float h2_low(uint32_t v)  { __half2 h = *(__half2*)&v; return __low2float(h); }
__device__ __forceinline__ float h2_high(uint32_t v) { __half2 h = *(__half2*)&v; return __high2float(h); }
__device__ __forceinline__ void ldsm4(uint32_t* r, uint32_t addr) {
    asm volatile("ldmatrix.sync.aligned.m8n8.x4.shared.b16 {%0,%1,%2,%3}, [%4];"
                 : "=r"(r[0]), "=r"(r[1]), "=r"(r[2]), "=r"(r[3]) : "r"(addr));
}
__device__ __forceinline__ void mma_h(uint32_t* d, const uint32_t* a, uint32_t b0, uint32_t b1) {
    asm volatile("mma.sync.aligned.m16n8k16.row.col.f16.f16.f16.f16 "
                 "{%0,%1}, {%2,%3,%4,%5}, {%6,%7}, {%0,%1};"
                 : "+r"(d[0]), "+r"(d[1])
                 : "r"(a[0]), "r"(a[1]), "r"(a[2]), "r"(a[3]), "r"(b0), "r"(b1));
}
#define CP_ASYNC16(sa, ga) \
    asm volatile("cp.async.cg.shared.global [%0], [%1], 16;" :: "r"(sa), "l"(ga))
#define CP_COMMIT() asm volatile("cp.async.commit_group;" ::: "memory")
#define CP_WAIT1()  asm volatile("cp.async.wait_group 1;" ::: "memory")

// jobs: (I, k), I = 0..63 (128-row A strip), cols [128I + 256k, +256), k < 32 - (I>>1)
__device__ __forceinline__ void job_ij(int g, int& I, int& k) {
    I = 0;
    while (g >= 32 - (I >> 1)) { g -= 32 - (I >> 1); I++; }
    k = g;
}
__device__ __forceinline__ void job_adv(int& I, int& k) {
    if (++k == 32 - (I >> 1)) { ++I; k = 0; }
}

// ---------------------------------------------------------------------------
// Kernel 1: normalize + pre-scale + fp16 cast + fp32-exact positives (2 pairs/warp)
// ---------------------------------------------------------------------------
__global__ void k_prep(const float* __restrict__ zi, const float* __restrict__ zj) {
    int warp = threadIdx.x >> 5, lane = threadIdx.x & 31;
    int p1 = blockIdx.x * 8 + warp;
    int p2 = p1 + 2048;
    float4 a1 = ((const float4*)(zi + (size_t)p1 * D))[lane];
    float4 b1 = ((const float4*)(zj + (size_t)p1 * D))[lane];
    float4 a2 = ((const float4*)(zi + (size_t)p2 * D))[lane];
    float4 b2 = ((const float4*)(zj + (size_t)p2 * D))[lane];
    float s0 = a1.x*a1.x + a1.y*a1.y + a1.z*a1.z + a1.w*a1.w;
    float s1 = b1.x*b1.x + b1.y*b1.y + b1.z*b1.z + b1.w*b1.w;
    float s2 = a1.x*b1.x + a1.y*b1.y + a1.z*b1.z + a1.w*b1.w;
    float s3 = a2.x*a2.x + a2.y*a2.y + a2.z*a2.z + a2.w*a2.w;
    float s4 = b2.x*b2.x + b2.y*b2.y + b2.z*b2.z + b2.w*b2.w;
    float s5 = a2.x*b2.x + a2.y*b2.y + a2.z*b2.z + a2.w*b2.w;
    #pragma unroll
    for (int o = 16; o; o >>= 1) {
        s0 += __shfl_xor_sync(0xffffffffu, s0, o);
        s1 += __shfl_xor_sync(0xffffffffu, s1, o);
        s2 += __shfl_xor_sync(0xffffffffu, s2, o);
        s3 += __shfl_xor_sync(0xffffffffu, s3, o);
        s4 += __shfl_xor_sync(0xffffffffu, s4, o);
        s5 += __shfl_xor_sync(0xffffffffu, s5, o);
    }
    float ia1 = 1.0f / fmaxf(sqrtf(s0), 1e-8f);
    float ib1 = 1.0f / fmaxf(sqrtf(s1), 1e-8f);
    float ia2 = 1.0f / fmaxf(sqrtf(s3), 1e-8f);
    float ib2 = 1.0f / fmaxf(sqrtf(s4), 1e-8f);
    if (lane == 0) {
        float q1 = s2 * ia1 * ib1, q2 = s5 * ia2 * ib2;
        g_pos[p1] = q1; g_pos[p1 + NROWS] = q1;
        g_pos[p2] = q2; g_pos[p2 + NROWS] = q2;
    }
    float fa1 = ia1 * PSC, fb1 = ib1 * PSC, fa2 = ia2 * PSC, fb2 = ib2 * PSC;
    __half h[4];
    h[0]=__float2half(a1.x*fa1); h[1]=__float2half(a1.y*fa1); h[2]=__float2half(a1.z*fa1); h[3]=__float2half(a1.w*fa1);
    *(uint2*)(g_h + (size_t)p1 * D + lane * 4) = *(uint2*)h;
    h[0]=__float2half(b1.x*fb1); h[1]=__float2half(b1.y*fb1); h[2]=__float2half(b1.z*fb1); h[3]=__float2half(b1.w*fb1);
    *(uint2*)(g_h + (size_t)(p1 + NROWS) * D + lane * 4) = *(uint2*)h;
    h[0]=__float2half(a2.x*fa2); h[1]=__float2half(a2.y*fa2); h[2]=__float2half(a2.z*fa2); h[3]=__float2half(a2.w*fa2);
    *(uint2*)(g_h + (size_t)p2 * D + lane * 4) = *(uint2*)h;
    h[0]=__float2half(b2.x*fb2); h[1]=__float2half(b2.y*fb2); h[2]=__float2half(b2.z*fb2); h[3]=__float2half(b2.w*fb2);
    *(uint2*)(g_h + (size_t)(p2 + NROWS) * D + lane * 4) = *(uint2*)h;
}

// ---------------- tile loaders ----------------
// B: 256 rows x 128 fp16 (256B rows), XOR-swizzled 16B chunks
__device__ __forceinline__ void load_B_async(uint32_t sb, uint32_t off, int rowBase, int t) {
    #pragma unroll
    for (int rep = 0; rep < 16; rep++) {
        int idx = rep * 256 + t;          // 0..4095
        int row = idx >> 4, ch = idx & 15;
        uint32_t so = off + (uint32_t)(row * 256) + ((uint32_t)(ch ^ (row & 7)) << 4);
        CP_ASYNC16(sb + so, g_h + (size_t)(rowBase + row) * D + ch * 8);
    }
}
__device__ __forceinline__ void load_A_plain(char* sm, int rowBase, int t) {
    #pragma unroll
    for (int rep = 0; rep < 8; rep++) {
        int idx = rep * 256 + t;
        int row = idx >> 4, ch = idx & 15;
        uint32_t so = (uint32_t)(row * 256) + ((uint32_t)(ch ^ (row & 7)) << 4);
        *(uint4*)(sm + SM_A + so) = *(const uint4*)(g_h + (size_t)(rowBase + row) * D + ch * 8);
    }
}

// ---------------------------------------------------------------------------
// tile body: 64x64 warp tile, MMA(cur) + prev-bank ex2 interleave.
// ex2 mapping: (ks, mt, nt==0) -> dP[ks>>1][((ks&1)<<2)|mt][0]; nt==4 -> [1].
// Covers 4x8x2 = 64 regs exactly once.
// ---------------------------------------------------------------------------
template <bool HP>
__device__ __forceinline__ void tile_body(
    uint32_t (&dC)[4][8][2], uint32_t (&dP)[4][8][2],
    uint32_t bBase, const uint32_t (&aRow)[4], const uint32_t (&bRow)[4],
    int c4A, int c4B, int r7)
{
    #pragma unroll
    for (int mt = 0; mt < 4; mt++)
        #pragma unroll
        for (int nt = 0; nt < 8; nt++) { dC[mt][nt][0] = NEG_C2; dC[mt][nt][1] = NEG_C2; }

    #pragma unroll
    for (int ks = 0; ks < 8; ks++) {
        uint32_t ah[4][4], bh[16];
        const uint32_t offA = (uint32_t)(((2 * ks + c4A) ^ r7) << 4);
        const uint32_t offB = (uint32_t)(((2 * ks + c4B) ^ r7) << 4);
        #pragma unroll
        for (int mt = 0; mt < 4; mt++) ldsm4(ah[mt], aRow[mt] + offA);
        #pragma unroll
        for (int g = 0; g < 4; g++) ldsm4(bh + g * 4, bBase + bRow[g] + offB);
        #pragma unroll
        for (int mt = 0; mt < 4; mt++) {
            #pragma unroll
            for (int nt = 0; nt < 8; nt++) {
                mma_h(dC[mt][nt], ah[mt], bh[nt * 2], bh[nt * 2 + 1]);
                if (HP && nt == 0) ex2_h2_ip(dP[ks >> 1][((ks & 1) << 2) | mt][0]);
                if (HP && nt == 4) ex2_h2_ip(dP[ks >> 1][((ks & 1) << 2) | mt][1]);
            }
        }
    }
}

// epilogue reduce for job (Ie, ke): diag substitute (ke==0), phantom mask,
// row trees -> rowred[128][4], col trees -> colred[256][2]
__device__ __forceinline__ void epi_reduce(
    char* sm, uint32_t (&d)[4][8][2], int par, int Ie, int ke, bool phantom,
    int lane, int warpM, int warpN, int rq, int cq, uint32_t DIAG_H16)
{
    if (ke == 0) {
        #pragma unroll
        for (int mt = 0; mt < 4; mt++) {
            #pragma unroll
            for (int q = 0; q < 2; q++) {
                const int r = warpM * 64 + mt * 16 + q * 8 + rq;     // 0..127
                #pragma unroll
                for (int nt = 0; nt < 8; nt++) {
                    const int c0 = warpN * 64 + nt * 8 + cq;          // 0..255
                    if (r == c0)     d[mt][nt][q] = (d[mt][nt][q] & 0xFFFF0000u) | DIAG_H16;
                    if (r == c0 + 1) d[mt][nt][q] = (d[mt][nt][q] & 0x0000FFFFu) | (DIAG_H16 << 16);
                }
            }
        }
    }
    float* rowred = (float*)(sm + SM_RED(par));            // [128][4]
    float* colred = (float*)(sm + SM_RED(par) + 2048);     // [256][2]
    const bool maskRow = phantom && (warpN >= 2);          // phantom cols contribute 0 to rows
    #pragma unroll
    for (int mt = 0; mt < 4; mt++) {
        #pragma unroll
        for (int q = 0; q < 2; q++) {
            uint32_t p0 = hadd2(d[mt][0][q], d[mt][1][q]);
            uint32_t p1 = hadd2(d[mt][2][q], d[mt][3][q]);
            uint32_t p2 = hadd2(d[mt][4][q], d[mt][5][q]);
            uint32_t p3 = hadd2(d[mt][6][q], d[mt][7][q]);
            uint32_t rp = hadd2(hadd2(p0, p1), hadd2(p2, p3));
            float v = h2_low(rp) + h2_high(rp);
            v += __shfl_xor_sync(0xffffffffu, v, 1);
            v += __shfl_xor_sync(0xffffffffu, v, 2);
            if ((lane & 3) == 0) {
                int r = warpM * 64 + mt * 16 + q * 8 + rq;
                rowred[r * 4 + warpN] = maskRow ? 0.0f : v;
            }
        }
    }
    #pragma unroll
    for (int nt = 0; nt < 8; nt++) {
        uint32_t cp = hadd2(hadd2(hadd2(d[0][nt][0], d[0][nt][1]),
                                  hadd2(d[1][nt][0], d[1][nt][1])),
                            hadd2(hadd2(d[2][nt][0], d[2][nt][1]),
                                  hadd2(d[3][nt][0], d[3][nt][1])));
        cp = hadd2(cp, (uint32_t)__shfl_xor_sync(0xffffffffu, (int)cp, 4));
        cp = hadd2(cp, (uint32_t)__shfl_xor_sync(0xffffffffu, (int)cp, 8));
        cp = hadd2(cp, (uint32_t)__shfl_xor_sync(0xffffffffu, (int)cp, 16));
        if (lane < 4) {
            int c0 = warpN * 64 + nt * 8 + (lane & 3) * 2;
            colred[c0 * 2 + warpM]       = h2_low(cp);
            colred[(c0 + 1) * 2 + warpM] = h2_high(cp);
        }
    }
}
// write row parts (slot ke) and col parts (slot 32+Ie); self-block cols skipped
__device__ __forceinline__ void epi_write(char* sm, int par, int Ie, int ke, int c0e, int t) {
    float* rowred = (float*)(sm + SM_RED(par));
    float* colred = (float*)(sm + SM_RED(par) + 2048);
    if (t < 128) {
        float s = rowred[t * 4] + rowred[t * 4 + 1] + rowred[t * 4 + 2] + rowred[t * 4 + 3];
        g_part[((size_t)(Ie * 128 + t)) * 128 + ke] = s;
    }
    int c = t;                                  // 0..255
    if (!(ke == 0 && c < 128)) {                // skip self-block cols
        float s = colred[c * 2] + colred[c * 2 + 1];
        g_part[((size_t)(c0e + c)) * 128 + 32 + Ie] = s;   // phantom cols land in padded rows
    }
}

// ---------------------------------------------------------------------------
// Kernel 2: triangle sim-GEMM, 128x256 jobs, pipelined epilogue.
// ---------------------------------------------------------------------------
__global__ __launch_bounds__(256, 1)
void k_main() {
    extern __shared__ char sm[];
    const uint32_t sb = smem_u32(sm);
    const int t = threadIdx.x, lane = t & 31, wid = t >> 5;
    const int warpM = wid >> 2, warpN = wid & 3;   // 2 x 4 warps, 64x64 tiles

    const __half diag_h = __float2half(DIAG_F);
    const uint32_t DIAG_H16 = (uint32_t)*(const uint16_t*)&diag_h;

    const int jb = (int)(((long)blockIdx.x * NJOBS) / GRID_MAIN);
    const int je = (int)(((long)(blockIdx.x + 1) * NJOBS) / GRID_MAIN);
    const int njobs = je - jb;

    const int r7   = lane & 7;
    const int rowA = (lane & 7) + ((lane >> 3) & 1) * 8;  const int c4A = lane >> 4;
    const int rowB = (lane & 7) + ((lane >> 4) << 3);     const int c4B = (lane >> 3) & 1;
    const int rq = lane >> 2;
    const int cq = (lane & 3) * 2;

    uint32_t aRow[4];
    #pragma unroll
    for (int mt = 0; mt < 4; mt++)
        aRow[mt] = sb + SM_A + (uint32_t)((warpM * 64 + mt * 16 + rowA) * 256);
    uint32_t bRow[4];
    #pragma unroll
    for (int g = 0; g < 4; g++) bRow[g] = (uint32_t)((warpN * 64 + g * 16 + rowB) * 256);

    uint32_t dA[4][8][2], dB[4][8][2];

    int Im, Km; job_ij(jb, Im, Km);
    int Ip = Im, Kp = Km;
    int Ia;

    // prologue
    load_B_async(sb, SM_B(0), 128 * Ip + 256 * Kp, t); CP_COMMIT(); job_adv(Ip, Kp);
    load_B_async(sb, SM_B(1), 128 * Ip + 256 * Kp, t); CP_COMMIT(); job_adv(Ip, Kp);
    load_A_plain(sm, Im * 128, t); Ia = Im;
    CP_WAIT1();
    __syncthreads();
    tile_body<false>(dA, dB, sb + SM_B(0), aRow, bRow, c4A, c4B, r7);
    __syncthreads();
    if (2 < njobs) { load_B_async(sb, SM_B(0), 128 * Ip + 256 * Kp, t); job_adv(Ip, Kp); }
    CP_COMMIT();
    int Ie = Im, Ke = Km; job_adv(Im, Km);

    for (int jj = 1; jj < njobs; jj++) {
        CP_WAIT1();
        __syncthreads();
        if (Im != Ia) { load_A_plain(sm, Im * 128, t); __syncthreads(); Ia = Im; }
        const uint32_t bBase = sb + SM_B(jj & 1);
        const int par = jj & 1;
        const bool phant = (Ie & 1) && (Ke == (32 - (Ie >> 1)) - 1);
        if (par) {
            tile_body<true>(dB, dA, bBase, aRow, bRow, c4A, c4B, r7);
            epi_reduce(sm, dA, par, Ie, Ke, phant, lane, warpM, warpN, rq, cq, DIAG_H16);
        } else {
            tile_body<true>(dA, dB, bBase, aRow, bRow, c4A, c4B, r7);
            epi_reduce(sm, dB, par, Ie, Ke, phant, lane, warpM, warpN, rq, cq, DIAG_H16);
        }
        __syncthreads();
        if (jj + 2 < njobs) { load_B_async(sb, SM_B(jj & 1), 128 * Ip + 256 * Kp, t); job_adv(Ip, Kp); }
        CP_COMMIT();
        epi_write(sm, par, Ie, Ke, 128 * Ie + 256 * Ke, t);
        Ie = Im; Ke = Km; job_adv(Im, Km);
    }

    // final epilogue on the last bank
    {
        const int par = njobs & 1;
        const bool phant = (Ie & 1) && (Ke == (32 - (Ie >> 1)) - 1);
        if ((njobs - 1) & 1) {
            #pragma unroll
            for (int mt = 0; mt < 4; mt++)
                #pragma unroll
                for (int nt = 0; nt < 8; nt++) { ex2_h2_ip(dB[mt][nt][0]); ex2_h2_ip(dB[mt][nt][1]); }
            epi_reduce(sm, dB, par, Ie, Ke, phant, lane, warpM, warpN, rq, cq, DIAG_H16);
        } else {
            #pragma unroll
            for (int mt = 0; mt < 4; mt++)
                #pragma unroll
                for (int nt = 0; nt < 8; nt++) { ex2_h2_ip(dA[mt][nt][0]); ex2_h2_ip(dA[mt][nt][1]); }
            epi_reduce(sm, dA, par, Ie, Ke, phant, lane, warpM, warpN, rq, cq, DIAG_H16);
        }
        __syncthreads();
        epi_write(sm, par, Ie, Ke, 128 * Ie + 256 * Ke, t);
    }
}

// ---------------------------------------------------------------------------
// Kernel 3: per-row loss (coalesced float4 reads over 128 slots) + reduction.
// ---------------------------------------------------------------------------
__global__ void k_tail(float* __restrict__ out) {
    __shared__ float red[256];
    __shared__ bool isLast;
    int r = blockIdx.x * 256 + threadIdx.x;
    const float4* base = (const float4*)(g_part + (size_t)r * 128);
    float S = 0.0f;
    #pragma unroll
    for (int q = 0; q < 32; q++) {
        float4 v = base[q];
        S += v.x + v.y + v.z + v.w;
    }
    float p = g_pos[r];
    float Sf = S + expf(fmaf(10.0f, p, -TAIL_C));
    red[threadIdx.x] = logf(Sf) + TAIL_C - 10.0f * p;
    __syncthreads();
    for (int s = 128; s; s >>= 1) {
        if (threadIdx.x < s) red[threadIdx.x] += red[threadIdx.x + s];
        __syncthreads();
    }
    if (threadIdx.x == 0) {
        g_bsum[blockIdx.x] = red[0];
        __threadfence();
        unsigned int done = atomicAdd(&g_cnt, 1u);
        isLast = (done == 31u);
    }
    __syncthreads();
    if (isLast && threadIdx.x == 0) {
        float acc = 0.0f;
        #pragma unroll
        for (int b = 0; b < 32; b++) acc += ((volatile float*)g_bsum)[b];
        out[0] = acc * (1.0f / (float)TWO_N);
        g_cnt = 0;
    }
}

// ---------------------------------------------------------------------------
extern "C" void kernel_launch(void* const* d_in, const int* in_sizes, int n_in,
                              void* d_out, int out_size) {
    const float* zi = (const float*)d_in[0];
    const float* zj = (const float*)d_in[1];
    float* out = (float*)d_out;

    cudaFuncSetAttribute(k_main, cudaFuncAttributeMaxDynamicSharedMemorySize, SMEM_BYTES);

    k_prep<<<256, 256>>>(zi, zj);
    k_main<<<GRID_MAIN, 256, SMEM_BYTES>>>();
    k_tail<<<32, 256>>>(out);
}

// round 14
// speedup vs baseline: 1.0998x; 1.0998x over previous
#include <cuda_runtime.h>
#include <cuda_fp16.h>
#include <math.h>
#include <stdint.h>

#define NROWS 4096
#define TWO_N 8192
#define D 128
#define NTILE 64
#define NJOBS 2080                  // 64*65/2 triangle tiles
#define GRID_MAIN 296               // 2 CTAs per SM
#define PSC 3.798282565009841f      // sqrt(10/ln2) pre-scale
#define NEG_C2 0xCB37CB37u          // packed f16x2 (-C,-C), C = 14.4296875 (f16-exact)
#define TAIL_C 10.00189733f         // C * ln(2)
#define DIAG_F 0.99810459f          // exact diag term e^(10 - TAIL_C)

// ---------------- device scratch (allocation-free) ----------------
__device__ __half         g_h[TWO_N * D];
__device__ float          g_pos[TWO_N];
__device__ float          g_part[TWO_N * NTILE];   // [row][J] -- coalesced tail reads
__device__ float          g_bsum[32];
__device__ unsigned int   g_cnt;

// ---------------- smem map (dynamic): 104448 B/CTA -> 2 CTAs/SM ----------------
#define SM_A      0
#define SM_B(s)   (32768 + (s) * 32768)
#define SM_RED(b) (98304 + (b) * 3072)     // rowred[128][4] (2048B) + colred[128][2] (1024B)
#define SMEM_BYTES 104448

// ---------------- helpers ----------------
__device__ __forceinline__ uint32_t smem_u32(const void* p) {
    uint32_t a;
    asm("{ .reg .u64 t; cvta.to.shared.u64 t, %1; cvt.u32.u64 %0, t; }" : "=r"(a) : "l"(p));
    return a;
}
__device__ __forceinline__ void ex2_h2_ip(uint32_t& x) {
    asm volatile("ex2.approx.f16x2 %0, %0;" : "+r"(x));
}
__device__ __forceinline__ uint32_t hadd2(uint32_t a, uint32_t b) {
    uint32_t r; asm("add.rn.f16x2 %0, %1, %2;" : "=r"(r) : "r"(a), "r"(b)); return r;
}
__device__ __forceinline__ float h2_low(uint32_t v)  { __half2 h = *(__half2*)&v; return __low2float(h); }
__device__ __forceinline__ float h2_high(uint32_t v) { __half2 h = *(__half2*)&v; return __high2float(h); }
__device__ __forceinline__ void ldsm4(uint32_t* r, uint32_t addr) {
    asm volatile("ldmatrix.sync.aligned.m8n8.x4.shared.b16 {%0,%1,%2,%3}, [%4];"
                 : "=r"(r[0]), "=r"(r[1]), "=r"(r[2]), "=r"(r[3]) : "r"(addr));
}
__device__ __forceinline__ void mma_h(uint32_t* d, const uint32_t* a, uint32_t b0, uint32_t b1) {
    asm volatile("mma.sync.aligned.m16n8k16.row.col.f16.f16.f16.f16 "
                 "{%0,%1}, {%2,%3,%4,%5}, {%6,%7}, {%0,%1};"
                 : "+r"(d[0]), "+r"(d[1])
                 : "r"(a[0]), "r"(a[1]), "r"(a[2]), "r"(a[3]), "r"(b0), "r"(b1));
}
#define CP_ASYNC16(sa, ga) \
    asm volatile("cp.async.cg.shared.global [%0], [%1], 16;" :: "r"(sa), "l"(ga))
#define CP_COMMIT() asm volatile("cp.async.commit_group;" ::: "memory")
#define CP_WAIT1()  asm volatile("cp.async.wait_group 1;" ::: "memory")

__device__ __forceinline__ void job_ij(int g, int& I, int& J) {
    int i = 0, off = 0;
    while (off + (NTILE - i) <= g) { off += NTILE - i; i++; }
    I = i; J = i + (g - off);
}
__device__ __forceinline__ void job_adv(int& I, int& J) {
    if (++J == NTILE) { ++I; J = I; }
}

// ---------------------------------------------------------------------------
// Kernel 1: normalize + pre-scale + fp16 cast + fp32-exact positives (2 pairs/warp)
// ---------------------------------------------------------------------------
__global__ void k_prep(const float* __restrict__ zi, const float* __restrict__ zj) {
    int warp = threadIdx.x >> 5, lane = threadIdx.x & 31;
    int p1 = blockIdx.x * 8 + warp;
    int p2 = p1 + 2048;
    float4 a1 = ((const float4*)(zi + (size_t)p1 * D))[lane];
    float4 b1 = ((const float4*)(zj + (size_t)p1 * D))[lane];
    float4 a2 = ((const float4*)(zi + (size_t)p2 * D))[lane];
    float4 b2 = ((const float4*)(zj + (size_t)p2 * D))[lane];
    float s0 = a1.x*a1.x + a1.y*a1.y + a1.z*a1.z + a1.w*a1.w;
    float s1 = b1.x*b1.x + b1.y*b1.y + b1.z*b1.z + b1.w*b1.w;
    float s2 = a1.x*b1.x + a1.y*b1.y + a1.z*b1.z + a1.w*b1.w;
    float s3 = a2.x*a2.x + a2.y*a2.y + a2.z*a2.z + a2.w*a2.w;
    float s4 = b2.x*b2.x + b2.y*b2.y + b2.z*b2.z + b2.w*b2.w;
    float s5 = a2.x*b2.x + a2.y*b2.y + a2.z*b2.z + a2.w*b2.w;
    #pragma unroll
    for (int o = 16; o; o >>= 1) {
        s0 += __shfl_xor_sync(0xffffffffu, s0, o);
        s1 += __shfl_xor_sync(0xffffffffu, s1, o);
        s2 += __shfl_xor_sync(0xffffffffu, s2, o);
        s3 += __shfl_xor_sync(0xffffffffu, s3, o);
        s4 += __shfl_xor_sync(0xffffffffu, s4, o);
        s5 += __shfl_xor_sync(0xffffffffu, s5, o);
    }
    float ia1 = 1.0f / fmaxf(sqrtf(s0), 1e-8f);
    float ib1 = 1.0f / fmaxf(sqrtf(s1), 1e-8f);
    float ia2 = 1.0f / fmaxf(sqrtf(s3), 1e-8f);
    float ib2 = 1.0f / fmaxf(sqrtf(s4), 1e-8f);
    if (lane == 0) {
        float q1 = s2 * ia1 * ib1, q2 = s5 * ia2 * ib2;
        g_pos[p1] = q1; g_pos[p1 + NROWS] = q1;
        g_pos[p2] = q2; g_pos[p2 + NROWS] = q2;
    }
    float fa1 = ia1 * PSC, fb1 = ib1 * PSC, fa2 = ia2 * PSC, fb2 = ib2 * PSC;
    __half h[4];
    h[0]=__float2half(a1.x*fa1); h[1]=__float2half(a1.y*fa1); h[2]=__float2half(a1.z*fa1); h[3]=__float2half(a1.w*fa1);
    *(uint2*)(g_h + (size_t)p1 * D + lane * 4) = *(uint2*)h;
    h[0]=__float2half(b1.x*fb1); h[1]=__float2half(b1.y*fb1); h[2]=__float2half(b1.z*fb1); h[3]=__float2half(b1.w*fb1);
    *(uint2*)(g_h + (size_t)(p1 + NROWS) * D + lane * 4) = *(uint2*)h;
    h[0]=__float2half(a2.x*fa2); h[1]=__float2half(a2.y*fa2); h[2]=__float2half(a2.z*fa2); h[3]=__float2half(a2.w*fa2);
    *(uint2*)(g_h + (size_t)p2 * D + lane * 4) = *(uint2*)h;
    h[0]=__float2half(b2.x*fb2); h[1]=__float2half(b2.y*fb2); h[2]=__float2half(b2.z*fb2); h[3]=__float2half(b2.w*fb2);
    *(uint2*)(g_h + (size_t)(p2 + NROWS) * D + lane * 4) = *(uint2*)h;
}

// ---------------- tile loaders (XOR-swizzled 16B chunks, 256B rows) ----------------
__device__ __forceinline__ void load_B_async(uint32_t sb, uint32_t off, int rowBase, int t) {
    #pragma unroll
    for (int rep = 0; rep < 8; rep++) {
        int idx = rep * 256 + t;
        int row = idx >> 4, ch = idx & 15;
        uint32_t so = off + (uint32_t)(row * 256) + ((uint32_t)(ch ^ (row & 7)) << 4);
        CP_ASYNC16(sb + so, g_h + (size_t)(rowBase + row) * D + ch * 8);
    }
}
__device__ __forceinline__ void load_A_plain(char* sm, int rowBase, int t) {
    #pragma unroll
    for (int rep = 0; rep < 8; rep++) {
        int idx = rep * 256 + t;
        int row = idx >> 4, ch = idx & 15;
        uint32_t so = (uint32_t)(row * 256) + ((uint32_t)(ch ^ (row & 7)) << 4);
        *(uint4*)(sm + SM_A + so) = *(const uint4*)(g_h + (size_t)(rowBase + row) * D + ch * 8);
    }
}

// ---------------------------------------------------------------------------
// tile body: 64x32 warp tile, f16 accumulate, single bank
// ---------------------------------------------------------------------------
__device__ __forceinline__ void tile_body(
    uint32_t (&d)[4][4][2], uint32_t bBase,
    const uint32_t (&aRow)[4], const uint32_t (&bRow)[2],
    int c4A, int c4B, int r7)
{
    #pragma unroll
    for (int mt = 0; mt < 4; mt++)
        #pragma unroll
        for (int nt = 0; nt < 4; nt++) { d[mt][nt][0] = NEG_C2; d[mt][nt][1] = NEG_C2; }

    #pragma unroll
    for (int ks = 0; ks < 8; ks++) {
        uint32_t ah[4][4], bh[8];
        const uint32_t offA = (uint32_t)(((2 * ks + c4A) ^ r7) << 4);
        const uint32_t offB = (uint32_t)(((2 * ks + c4B) ^ r7) << 4);
        #pragma unroll
        for (int mt = 0; mt < 4; mt++) ldsm4(ah[mt], aRow[mt] + offA);
        #pragma unroll
        for (int g = 0; g < 2; g++) ldsm4(bh + g * 4, bBase + bRow[g] + offB);
        #pragma unroll
        for (int mt = 0; mt < 4; mt++)
            #pragma unroll
            for (int nt = 0; nt < 4; nt++)
                mma_h(d[mt][nt], ah[mt], bh[nt * 2], bh[nt * 2 + 1]);
    }
}

// epilogue: ex2 + exact-diag substitute + row/col trees -> red[par]
__device__ __forceinline__ void epi_reduce(
    char* sm, uint32_t (&d)[4][4][2], int par, int Ie, int Je,
    int lane, int warpM, int warpN, int rq, int cq, uint32_t DIAG_H16)
{
    #pragma unroll
    for (int mt = 0; mt < 4; mt++)
        #pragma unroll
        for (int nt = 0; nt < 4; nt++) {
            ex2_h2_ip(d[mt][nt][0]);
            ex2_h2_ip(d[mt][nt][1]);
        }
    if (Ie == Je) {
        #pragma unroll
        for (int mt = 0; mt < 4; mt++) {
            #pragma unroll
            for (int q = 0; q < 2; q++) {
                const int r = warpM * 64 + mt * 16 + q * 8 + rq;
                #pragma unroll
                for (int nt = 0; nt < 4; nt++) {
                    const int c0 = warpN * 32 + nt * 8 + cq;
                    if (r == c0)     d[mt][nt][q] = (d[mt][nt][q] & 0xFFFF0000u) | DIAG_H16;
                    if (r == c0 + 1) d[mt][nt][q] = (d[mt][nt][q] & 0x0000FFFFu) | (DIAG_H16 << 16);
                }
            }
        }
    }
    float* rowred = (float*)(sm + SM_RED(par));
    float* colred = (float*)(sm + SM_RED(par) + 2048);
    #pragma unroll
    for (int mt = 0; mt < 4; mt++) {
        #pragma unroll
        for (int q = 0; q < 2; q++) {
            uint32_t rp = hadd2(hadd2(d[mt][0][q], d[mt][1][q]),
                                hadd2(d[mt][2][q], d[mt][3][q]));
            float v = h2_low(rp) + h2_high(rp);
            v += __shfl_xor_sync(0xffffffffu, v, 1);
            v += __shfl_xor_sync(0xffffffffu, v, 2);
            if ((lane & 3) == 0) {
                int r = warpM * 64 + mt * 16 + q * 8 + rq;
                rowred[r * 4 + warpN] = v;
            }
        }
    }
    #pragma unroll
    for (int nt = 0; nt < 4; nt++) {
        uint32_t cp = hadd2(hadd2(hadd2(d[0][nt][0], d[0][nt][1]),
                                  hadd2(d[1][nt][0], d[1][nt][1])),
                            hadd2(hadd2(d[2][nt][0], d[2][nt][1]),
                                  hadd2(d[3][nt][0], d[3][nt][1])));
        cp = hadd2(cp, (uint32_t)__shfl_xor_sync(0xffffffffu, (int)cp, 4));
        cp = hadd2(cp, (uint32_t)__shfl_xor_sync(0xffffffffu, (int)cp, 8));
        cp = hadd2(cp, (uint32_t)__shfl_xor_sync(0xffffffffu, (int)cp, 16));
        if (lane < 4) {
            int c0 = warpN * 32 + nt * 8 + (lane & 3) * 2;
            colred[c0 * 2 + warpM]       = h2_low(cp);
            colred[(c0 + 1) * 2 + warpM] = h2_high(cp);
        }
    }
}
__device__ __forceinline__ void epi_write(char* sm, int par, int Ie, int Je, int t) {
    float* rowred = (float*)(sm + SM_RED(par));
    float* colred = (float*)(sm + SM_RED(par) + 2048);
    if (t < 128) {
        float s = rowred[t * 4] + rowred[t * 4 + 1] + rowred[t * 4 + 2] + rowred[t * 4 + 3];
        g_part[((size_t)(Ie * 128 + t)) * 64 + Je] = s;
    } else if (Je > Ie) {
        int c = t - 128;
        g_part[((size_t)(Je * 128 + c)) * 64 + Ie] = colred[c * 2] + colred[c * 2 + 1];
    }
}

// ---------------------------------------------------------------------------
// Kernel 2: triangle sim-GEMM; 296 CTAs (2/SM) so one CTA's MMA hides the
// other's epilogue/sync/wait. 2 syncs/tile; epi_write deferred past top-sync.
// ---------------------------------------------------------------------------
__global__ __launch_bounds__(256, 2)
void k_main() {
    extern __shared__ char sm[];
    const uint32_t sb = smem_u32(sm);
    const int t = threadIdx.x, lane = t & 31, wid = t >> 5;
    const int warpM = wid >> 2, warpN = wid & 3;

    const __half diag_h = __float2half(DIAG_F);
    const uint32_t DIAG_H16 = (uint32_t)*(const uint16_t*)&diag_h;

    const int jb = (int)(((long)blockIdx.x * NJOBS) / GRID_MAIN);
    const int je = (int)(((long)(blockIdx.x + 1) * NJOBS) / GRID_MAIN);
    const int njobs = je - jb;

    const int r7   = lane & 7;
    const int rowA = (lane & 7) + ((lane >> 3) & 1) * 8;  const int c4A = lane >> 4;
    const int rowB = (lane & 7) + ((lane >> 4) << 3);     const int c4B = (lane >> 3) & 1;
    const int rq = lane >> 2;
    const int cq = (lane & 3) * 2;

    uint32_t aRow[4];
    #pragma unroll
    for (int mt = 0; mt < 4; mt++)
        aRow[mt] = sb + SM_A + (uint32_t)((warpM * 64 + mt * 16 + rowA) * 256);
    uint32_t bRow[2];
    #pragma unroll
    for (int g = 0; g < 2; g++) bRow[g] = (uint32_t)((warpN * 32 + g * 16 + rowB) * 256);

    uint32_t d[4][4][2];

    int Ic, Jc; job_ij(jb, Ic, Jc);
    int Ip = Ic, Jp = Jc;
    int Ia = -1, prevI = 0, prevJ = 0;

    // prologue: prefetch B for jobs 0 and 1
    load_B_async(sb, SM_B(0), Jp * 128, t); CP_COMMIT(); job_adv(Ip, Jp);
    if (njobs > 1) { load_B_async(sb, SM_B(1), Jp * 128, t); job_adv(Ip, Jp); }
    CP_COMMIT();

    for (int jj = 0; jj < njobs; jj++) {
        CP_WAIT1();
        __syncthreads();                         // B[jj&1] ready; red[(jj-1)&1] complete
        if (jj > 0) epi_write(sm, (jj - 1) & 1, prevI, prevJ, t);
        if (Ic != Ia) { load_A_plain(sm, Ic * 128, t); __syncthreads(); Ia = Ic; }
        tile_body(d, sb + SM_B(jj & 1), aRow, bRow, c4A, c4B, r7);
        __syncthreads();                         // all warps done reading B[jj&1]
        if (jj + 2 < njobs) { load_B_async(sb, SM_B(jj & 1), Jp * 128, t); job_adv(Ip, Jp); }
        CP_COMMIT();
        epi_reduce(sm, d, jj & 1, Ic, Jc, lane, warpM, warpN, rq, cq, DIAG_H16);
        prevI = Ic; prevJ = Jc; job_adv(Ic, Jc);
    }
    __syncthreads();
    epi_write(sm, (njobs - 1) & 1, prevI, prevJ, t);
}

// ---------------------------------------------------------------------------
// Kernel 3: per-row loss (coalesced float4 reads) + reduction.
// ---------------------------------------------------------------------------
__global__ void k_tail(float* __restrict__ out) {
    __shared__ float red[256];
    __shared__ bool isLast;
    int r = blockIdx.x * 256 + threadIdx.x;
    const float4* base = (const float4*)(g_part + (size_t)r * 64);
    float S = 0.0f;
    #pragma unroll
    for (int q = 0; q < 16; q++) {
        float4 v = base[q];
        S += v.x + v.y + v.z + v.w;
    }
    float p = g_pos[r];
    float Sf = S + expf(fmaf(10.0f, p, -TAIL_C));
    red[threadIdx.x] = logf(Sf) + TAIL_C - 10.0f * p;
    __syncthreads();
    for (int s = 128; s; s >>= 1) {
        if (threadIdx.x < s) red[threadIdx.x] += red[threadIdx.x + s];
        __syncthreads();
    }
    if (threadIdx.x == 0) {
        g_bsum[blockIdx.x] = red[0];
        __threadfence();
        unsigned int done = atomicAdd(&g_cnt, 1u);
        isLast = (done == 31u);
    }
    __syncthreads();
    if (isLast && threadIdx.x == 0) {
        float acc = 0.0f;
        #pragma unroll
        for (int b = 0; b < 32; b++) acc += ((volatile float*)g_bsum)[b];
        out[0] = acc * (1.0f / (float)TWO_N);
        g_cnt = 0;
    }
}

// ---------------------------------------------------------------------------
extern "C" void kernel_launch(void* const* d_in, const int* in_sizes, int n_in,
                              void* d_out, int out_size) {
    const float* zi = (const float*)d_in[0];
    const float* zj = (const float*)d_in[1];
    float* out = (float*)d_out;

    cudaFuncSetAttribute(k_main, cudaFuncAttributeMaxDynamicSharedMemorySize, SMEM_BYTES);

    k_prep<<<256, 256>>>(zi, zj);
    k_main<<<GRID_MAIN, 256, SMEM_BYTES>>>();
    k_tail<<<32, 256>>>(out);
}

// round 15
// speedup vs baseline: 1.1633x; 1.0577x over previous
#include <cuda_runtime.h>
#include <cuda_fp16.h>
#include <math.h>
#include <stdint.h>

#define NROWS 4096
#define TWO_N 8192
#define D 128
#define NTILE 64
#define NJOBS 2080                  // 64*65/2 triangle tiles
#define GRID_MAIN 296               // 2 CTAs per SM
#define CTA_T 128                   // 4 warps, 2x2 grid of 64x64 warp tiles
#define PSC 3.798282565009841f      // sqrt(10/ln2) pre-scale
#define NEG_C2 0xCB37CB37u          // packed f16x2 (-C,-C), C = 14.4296875 (f16-exact)
#define TAIL_C 10.00189733f         // C * ln(2)
#define DIAG_F 0.99810459f          // exact diag term e^(10 - TAIL_C)

// ---------------- device scratch (allocation-free) ----------------
__device__ __half         g_h[TWO_N * D];
__device__ float          g_pos[TWO_N];
__device__ float          g_part[TWO_N * NTILE];   // [row][J] -- coalesced tail reads
__device__ float          g_bsum[32];
__device__ unsigned int   g_cnt;

// ---------------- smem map (dynamic): 102400 B/CTA -> 2 CTAs/SM ----------------
#define SM_A      0
#define SM_B(s)   (32768 + (s) * 32768)
#define SM_RED(b) (98304 + (b) * 2048)     // rowred[128][2] (1024B) + colred[128][2] (1024B)
#define SMEM_BYTES 102400

// ---------------- helpers ----------------
__device__ __forceinline__ uint32_t smem_u32(const void* p) {
    uint32_t a;
    asm("{ .reg .u64 t; cvta.to.shared.u64 t, %1; cvt.u32.u64 %0, t; }" : "=r"(a) : "l"(p));
    return a;
}
__device__ __forceinline__ void ex2_h2_ip(uint32_t& x) {
    asm volatile("ex2.approx.f16x2 %0, %0;" : "+r"(x));
}
__device__ __forceinline__ uint32_t hadd2(uint32_t a, uint32_t b) {
    uint32_t r; asm("add.rn.f16x2 %0, %1, %2;" : "=r"(r) : "r"(a), "r"(b)); return r;
}
__device__ __forceinline__ float h2_low(uint32_t v)  { __half2 h = *(__half2*)&v; return __low2float(h); }
__device__ __forceinline__ float h2_high(uint32_t v) { __half2 h = *(__half2*)&v; return __high2float(h); }
__device__ __forceinline__ void ldsm4(uint32_t* r, uint32_t addr) {
    asm volatile("ldmatrix.sync.aligned.m8n8.x4.shared.b16 {%0,%1,%2,%3}, [%4];"
                 : "=r"(r[0]), "=r"(r[1]), "=r"(r[2]), "=r"(r[3]) : "r"(addr));
}
__device__ __forceinline__ void mma_h(uint32_t* d, const uint32_t* a, uint32_t b0, uint32_t b1) {
    asm volatile("mma.sync.aligned.m16n8k16.row.col.f16.f16.f16.f16 "
                 "{%0,%1}, {%2,%3,%4,%5}, {%6,%7}, {%0,%1};"
                 : "+r"(d[0]), "+r"(d[1])
                 : "r"(a[0]), "r"(a[1]), "r"(a[2]), "r"(a[3]), "r"(b0), "r"(b1));
}
#define CP_ASYNC16(sa, ga) \
    asm volatile("cp.async.cg.shared.global [%0], [%1], 16;" :: "r"(sa), "l"(ga))
#define CP_COMMIT() asm volatile("cp.async.commit_group;" ::: "memory")
#define CP_WAIT1()  asm volatile("cp.async.wait_group 1;" ::: "memory")

__device__ __forceinline__ void job_ij(int g, int& I, int& J) {
    int i = 0, off = 0;
    while (off + (NTILE - i) <= g) { off += NTILE - i; i++; }
    I = i; J = i + (g - off);
}
__device__ __forceinline__ void job_adv(int& I, int& J) {
    if (++J == NTILE) { ++I; J = I; }
}

// ---------------------------------------------------------------------------
// Kernel 1: normalize + pre-scale + fp16 cast + fp32-exact positives.
// One warp per pair, 512 blocks (best measured variant).
// ---------------------------------------------------------------------------
__global__ void k_prep(const float* __restrict__ zi, const float* __restrict__ zj) {
    int warp = threadIdx.x >> 5, lane = threadIdx.x & 31;
    int p = blockIdx.x * 8 + warp;
    float4 a = ((const float4*)(zi + (size_t)p * D))[lane];
    float4 b = ((const float4*)(zj + (size_t)p * D))[lane];
    float sa = a.x*a.x + a.y*a.y + a.z*a.z + a.w*a.w;
    float sb = b.x*b.x + b.y*b.y + b.z*b.z + b.w*b.w;
    float dp = a.x*b.x + a.y*b.y + a.z*b.z + a.w*b.w;
    #pragma unroll
    for (int o = 16; o; o >>= 1) {
        sa += __shfl_xor_sync(0xffffffffu, sa, o);
        sb += __shfl_xor_sync(0xffffffffu, sb, o);
        dp += __shfl_xor_sync(0xffffffffu, dp, o);
    }
    float ia = 1.0f / fmaxf(sqrtf(sa), 1e-8f);
    float ib = 1.0f / fmaxf(sqrtf(sb), 1e-8f);
    if (lane == 0) {
        float pos = dp * ia * ib;
        g_pos[p] = pos;
        g_pos[p + NROWS] = pos;
    }
    float fa = ia * PSC, fb = ib * PSC;
    __half ha[4], hb[4];
    ha[0] = __float2half(a.x*fa); ha[1] = __float2half(a.y*fa);
    ha[2] = __float2half(a.z*fa); ha[3] = __float2half(a.w*fa);
    hb[0] = __float2half(b.x*fb); hb[1] = __float2half(b.y*fb);
    hb[2] = __float2half(b.z*fb); hb[3] = __float2half(b.w*fb);
    *(uint2*)(g_h + (size_t)p * D + lane * 4)           = *(uint2*)ha;
    *(uint2*)(g_h + (size_t)(p + NROWS) * D + lane * 4) = *(uint2*)hb;
}

// ---------------- tile loaders (XOR-swizzled 16B chunks, 256B rows), 128 thr ----
__device__ __forceinline__ void load_B_async(uint32_t sb, uint32_t off, int rowBase, int t) {
    #pragma unroll
    for (int rep = 0; rep < 16; rep++) {
        int idx = rep * CTA_T + t;        // 0..2047
        int row = idx >> 4, ch = idx & 15;
        uint32_t so = off + (uint32_t)(row * 256) + ((uint32_t)(ch ^ (row & 7)) << 4);
        CP_ASYNC16(sb + so, g_h + (size_t)(rowBase + row) * D + ch * 8);
    }
}
__device__ __forceinline__ void load_A_plain(char* sm, int rowBase, int t) {
    #pragma unroll
    for (int rep = 0; rep < 16; rep++) {
        int idx = rep * CTA_T + t;
        int row = idx >> 4, ch = idx & 15;
        uint32_t so = (uint32_t)(row * 256) + ((uint32_t)(ch ^ (row & 7)) << 4);
        *(uint4*)(sm + SM_A + so) = *(const uint4*)(g_h + (size_t)(rowBase + row) * D + ch * 8);
    }
}

// ---------------------------------------------------------------------------
// tile body: 64x64 warp tile (mt 4 x nt 8), f16 accumulate, single bank
// ---------------------------------------------------------------------------
__device__ __forceinline__ void tile_body(
    uint32_t (&d)[4][8][2], uint32_t bBase,
    const uint32_t (&aRow)[4], const uint32_t (&bRow)[4],
    int c4A, int c4B, int r7)
{
    #pragma unroll
    for (int mt = 0; mt < 4; mt++)
        #pragma unroll
        for (int nt = 0; nt < 8; nt++) { d[mt][nt][0] = NEG_C2; d[mt][nt][1] = NEG_C2; }

    #pragma unroll
    for (int ks = 0; ks < 8; ks++) {
        uint32_t ah[4][4], bh[16];
        const uint32_t offA = (uint32_t)(((2 * ks + c4A) ^ r7) << 4);
        const uint32_t offB = (uint32_t)(((2 * ks + c4B) ^ r7) << 4);
        #pragma unroll
        for (int mt = 0; mt < 4; mt++) ldsm4(ah[mt], aRow[mt] + offA);
        #pragma unroll
        for (int g = 0; g < 4; g++) ldsm4(bh + g * 4, bBase + bRow[g] + offB);
        #pragma unroll
        for (int mt = 0; mt < 4; mt++)
            #pragma unroll
            for (int nt = 0; nt < 8; nt++)
                mma_h(d[mt][nt], ah[mt], bh[nt * 2], bh[nt * 2 + 1]);
    }
}

// epilogue: ex2 + exact-diag substitute + row/col trees -> red[par]
__device__ __forceinline__ void epi_reduce(
    char* sm, uint32_t (&d)[4][8][2], int par, int Ie, int Je,
    int lane, int warpM, int warpN, int rq, int cq, uint32_t DIAG_H16)
{
    #pragma unroll
    for (int mt = 0; mt < 4; mt++)
        #pragma unroll
        for (int nt = 0; nt < 8; nt++) {
            ex2_h2_ip(d[mt][nt][0]);
            ex2_h2_ip(d[mt][nt][1]);
        }
    if (Ie == Je) {
        #pragma unroll
        for (int mt = 0; mt < 4; mt++) {
            #pragma unroll
            for (int q = 0; q < 2; q++) {
                const int r = warpM * 64 + mt * 16 + q * 8 + rq;
                #pragma unroll
                for (int nt = 0; nt < 8; nt++) {
                    const int c0 = warpN * 64 + nt * 8 + cq;
                    if (r == c0)     d[mt][nt][q] = (d[mt][nt][q] & 0xFFFF0000u) | DIAG_H16;
                    if (r == c0 + 1) d[mt][nt][q] = (d[mt][nt][q] & 0x0000FFFFu) | (DIAG_H16 << 16);
                }
            }
        }
    }
    float* rowred = (float*)(sm + SM_RED(par));            // [128][2]
    float* colred = (float*)(sm + SM_RED(par) + 1024);     // [128][2]
    #pragma unroll
    for (int mt = 0; mt < 4; mt++) {
        #pragma unroll
        for (int q = 0; q < 2; q++) {
            uint32_t p0 = hadd2(d[mt][0][q], d[mt][1][q]);
            uint32_t p1 = hadd2(d[mt][2][q], d[mt][3][q]);
            uint32_t p2 = hadd2(d[mt][4][q], d[mt][5][q]);
            uint32_t p3 = hadd2(d[mt][6][q], d[mt][7][q]);
            uint32_t rp = hadd2(hadd2(p0, p1), hadd2(p2, p3));
            float v = h2_low(rp) + h2_high(rp);
            v += __shfl_xor_sync(0xffffffffu, v, 1);
            v += __shfl_xor_sync(0xffffffffu, v, 2);
            if ((lane & 3) == 0) {
                int r = warpM * 64 + mt * 16 + q * 8 + rq;
                rowred[r * 2 + warpN] = v;
            }
        }
    }
    #pragma unroll
    for (int nt = 0; nt < 8; nt++) {
        uint32_t cp = hadd2(hadd2(hadd2(d[0][nt][0], d[0][nt][1]),
                                  hadd2(d[1][nt][0], d[1][nt][1])),
                            hadd2(hadd2(d[2][nt][0], d[2][nt][1]),
                                  hadd2(d[3][nt][0], d[3][nt][1])));
        cp = hadd2(cp, (uint32_t)__shfl_xor_sync(0xffffffffu, (int)cp, 4));
        cp = hadd2(cp, (uint32_t)__shfl_xor_sync(0xffffffffu, (int)cp, 8));
        cp = hadd2(cp, (uint32_t)__shfl_xor_sync(0xffffffffu, (int)cp, 16));
        if (lane < 4) {
            int c0 = warpN * 64 + nt * 8 + (lane & 3) * 2;
            colred[c0 * 2 + warpM]       = h2_low(cp);
            colred[(c0 + 1) * 2 + warpM] = h2_high(cp);
        }
    }
}
__device__ __forceinline__ void epi_write(char* sm, int par, int Ie, int Je, int t) {
    float* rowred = (float*)(sm + SM_RED(par));
    float* colred = (float*)(sm + SM_RED(par) + 1024);
    float s = rowred[t * 2] + rowred[t * 2 + 1];
    g_part[((size_t)(Ie * 128 + t)) * 64 + Je] = s;
    if (Je > Ie) {
        float c = colred[t * 2] + colred[t * 2 + 1];
        g_part[((size_t)(Je * 128 + t)) * 64 + Ie] = c;
    }
}

// ---------------------------------------------------------------------------
// Kernel 2: triangle sim-GEMM; 296 CTAs x 128 threads (2 CTAs/SM).
// 64x64 warp tiles cut ldsm crossbar traffic 33%.
// ---------------------------------------------------------------------------
__global__ __launch_bounds__(CTA_T, 2)
void k_main() {
    extern __shared__ char sm[];
    const uint32_t sb = smem_u32(sm);
    const int t = threadIdx.x, lane = t & 31, wid = t >> 5;
    const int warpM = wid >> 1, warpN = wid & 1;   // 2 x 2 warp grid

    const __half diag_h = __float2half(DIAG_F);
    const uint32_t DIAG_H16 = (uint32_t)*(const uint16_t*)&diag_h;

    const int jb = (int)(((long)blockIdx.x * NJOBS) / GRID_MAIN);
    const int je = (int)(((long)(blockIdx.x + 1) * NJOBS) / GRID_MAIN);
    const int njobs = je - jb;

    const int r7   = lane & 7;
    const int rowA = (lane & 7) + ((lane >> 3) & 1) * 8;  const int c4A = lane >> 4;
    const int rowB = (lane & 7) + ((lane >> 4) << 3);     const int c4B = (lane >> 3) & 1;
    const int rq = lane >> 2;
    const int cq = (lane & 3) * 2;

    uint32_t aRow[4];
    #pragma unroll
    for (int mt = 0; mt < 4; mt++)
        aRow[mt] = sb + SM_A + (uint32_t)((warpM * 64 + mt * 16 + rowA) * 256);
    uint32_t bRow[4];
    #pragma unroll
    for (int g = 0; g < 4; g++)
        bRow[g] = (uint32_t)((warpN * 64 + g * 16 + rowB) * 256);

    uint32_t d[4][8][2];

    int Ic, Jc; job_ij(jb, Ic, Jc);
    int Ip = Ic, Jp = Jc;
    int Ia = -1, prevI = 0, prevJ = 0;

    load_B_async(sb, SM_B(0), Jp * 128, t); CP_COMMIT(); job_adv(Ip, Jp);
    if (njobs > 1) { load_B_async(sb, SM_B(1), Jp * 128, t); job_adv(Ip, Jp); }
    CP_COMMIT();

    for (int jj = 0; jj < njobs; jj++) {
        CP_WAIT1();
        __syncthreads();                         // B[jj&1] ready; red[(jj-1)&1] complete
        if (jj > 0) epi_write(sm, (jj - 1) & 1, prevI, prevJ, t);
        if (Ic != Ia) { load_A_plain(sm, Ic * 128, t); __syncthreads(); Ia = Ic; }
        tile_body(d, sb + SM_B(jj & 1), aRow, bRow, c4A, c4B, r7);
        __syncthreads();                         // all warps done reading B[jj&1]
        if (jj + 2 < njobs) { load_B_async(sb, SM_B(jj & 1), Jp * 128, t); job_adv(Ip, Jp); }
        CP_COMMIT();
        epi_reduce(sm, d, jj & 1, Ic, Jc, lane, warpM, warpN, rq, cq, DIAG_H16);
        prevI = Ic; prevJ = Jc; job_adv(Ic, Jc);
    }
    __syncthreads();
    epi_write(sm, (njobs - 1) & 1, prevI, prevJ, t);
}

// ---------------------------------------------------------------------------
// Kernel 3: per-row loss (coalesced float4 reads) + reduction.
// ---------------------------------------------------------------------------
__global__ void k_tail(float* __restrict__ out) {
    __shared__ float red[256];
    __shared__ bool isLast;
    int r = blockIdx.x * 256 + threadIdx.x;
    const float4* base = (const float4*)(g_part + (size_t)r * 64);
    float S = 0.0f;
    #pragma unroll
    for (int q = 0; q < 16; q++) {
        float4 v = base[q];
        S += v.x + v.y + v.z + v.w;
    }
    float p = g_pos[r];
    float Sf = S + expf(fmaf(10.0f, p, -TAIL_C));
    red[threadIdx.x] = logf(Sf) + TAIL_C - 10.0f * p;
    __syncthreads();
    for (int s = 128; s; s >>= 1) {
        if (threadIdx.x < s) red[threadIdx.x] += red[threadIdx.x + s];
        __syncthreads();
    }
    if (threadIdx.x == 0) {
        g_bsum[blockIdx.x] = red[0];
        __threadfence();
        unsigned int done = atomicAdd(&g_cnt, 1u);
        isLast = (done == 31u);
    }
    __syncthreads();
    if (isLast && threadIdx.x == 0) {
        float acc = 0.0f;
        #pragma unroll
        for (int b = 0; b < 32; b++) acc += ((volatile float*)g_bsum)[b];
        out[0] = acc * (1.0f / (float)TWO_N);
        g_cnt = 0;
    }
}

// ---------------------------------------------------------------------------
extern "C" void kernel_launch(void* const* d_in, const int* in_sizes, int n_in,
                              void* d_out, int out_size) {
    const float* zi = (const float*)d_in[0];
    const float* zj = (const float*)d_in[1];
    float* out = (float*)d_out;

    cudaFuncSetAttribute(k_main, cudaFuncAttributeMaxDynamicSharedMemorySize, SMEM_BYTES);

    k_prep<<<512, 256>>>(zi, zj);
    k_main<<<GRID_MAIN, CTA_T, SMEM_BYTES>>>();
    k_tail<<<32, 256>>>(out);
}

// round 16
// speedup vs baseline: 1.2271x; 1.0548x over previous
#include <cuda_runtime.h>
#include <cuda_fp16.h>
#include <math.h>
#include <stdint.h>

#define NROWS 4096
#define TWO_N 8192
#define D 128
#define NTILE 64
#define NJOBS 2080                  // 64*65/2 triangle tiles
#define GRID_MAIN 444               // 3 CTAs per SM
#define CTA_T 128                   // 4 warps, 2x2 grid of 64x64 warp tiles
#define PSC 3.798282565009841f      // sqrt(10/ln2) pre-scale
#define NEG_C2 0xCB37CB37u          // packed f16x2 (-C,-C), C = 14.4296875 (f16-exact)
#define TAIL_C 10.00189733f         // C * ln(2)
#define DIAG_F 0.99810459f          // exact diag term e^(10 - TAIL_C)

// ---------------- device scratch (allocation-free) ----------------
__device__ __half         g_h[TWO_N * D];
__device__ float          g_pos[TWO_N];
__device__ float          g_part[TWO_N * NTILE];   // [row][J] -- coalesced tail reads
__device__ float          g_bsum[32];
__device__ unsigned int   g_cnt;

// ---------------- smem map (dynamic): 69632 B/CTA -> 3 CTAs/SM ----------------
#define SM_A      0
#define SM_B      32768
#define SM_RED(b) (65536 + (b) * 2048)     // rowred[128][2] + colred[128][2]
#define SMEM_BYTES 69632

// ---------------- helpers ----------------
__device__ __forceinline__ uint32_t smem_u32(const void* p) {
    uint32_t a;
    asm("{ .reg .u64 t; cvta.to.shared.u64 t, %1; cvt.u32.u64 %0, t; }" : "=r"(a) : "l"(p));
    return a;
}
__device__ __forceinline__ void ex2_h2_ip(uint32_t& x) {
    asm volatile("ex2.approx.f16x2 %0, %0;" : "+r"(x));
}
__device__ __forceinline__ uint32_t hadd2(uint32_t a, uint32_t b) {
    uint32_t r; asm("add.rn.f16x2 %0, %1, %2;" : "=r"(r) : "r"(a), "r"(b)); return r;
}
__device__ __forceinline__ float h2_low(uint32_t v)  { __half2 h = *(__half2*)&v; return __low2float(h); }
__device__ __forceinline__ float h2_high(uint32_t v) { __half2 h = *(__half2*)&v; return __high2float(h); }
__device__ __forceinline__ void ldsm4(uint32_t* r, uint32_t addr) {
    asm volatile("ldmatrix.sync.aligned.m8n8.x4.shared.b16 {%0,%1,%2,%3}, [%4];"
                 : "=r"(r[0]), "=r"(r[1]), "=r"(r[2]), "=r"(r[3]) : "r"(addr));
}
__device__ __forceinline__ void mma_h(uint32_t* d, const uint32_t* a, uint32_t b0, uint32_t b1) {
    asm volatile("mma.sync.aligned.m16n8k16.row.col.f16.f16.f16.f16 "
                 "{%0,%1}, {%2,%3,%4,%5}, {%6,%7}, {%0,%1};"
                 : "+r"(d[0]), "+r"(d[1])
                 : "r"(a[0]), "r"(a[1]), "r"(a[2]), "r"(a[3]), "r"(b0), "r"(b1));
}
#define CP_ASYNC16(sa, ga) \
    asm volatile("cp.async.cg.shared.global [%0], [%1], 16;" :: "r"(sa), "l"(ga))
#define CP_COMMIT() asm volatile("cp.async.commit_group;" ::: "memory")
#define CP_WAIT0()  asm volatile("cp.async.wait_group 0;" ::: "memory")

__device__ __forceinline__ void job_ij(int g, int& I, int& J) {
    int i = 0, off = 0;
    while (off + (NTILE - i) <= g) { off += NTILE - i; i++; }
    I = i; J = i + (g - off);
}
__device__ __forceinline__ void job_adv(int& I, int& J) {
    if (++J == NTILE) { ++I; J = I; }
}

// ---------------------------------------------------------------------------
// Kernel 1: normalize + pre-scale + fp16 cast + fp32-exact positives.
// ---------------------------------------------------------------------------
__global__ void k_prep(const float* __restrict__ zi, const float* __restrict__ zj) {
    int warp = threadIdx.x >> 5, lane = threadIdx.x & 31;
    int p = blockIdx.x * 8 + warp;
    float4 a = ((const float4*)(zi + (size_t)p * D))[lane];
    float4 b = ((const float4*)(zj + (size_t)p * D))[lane];
    float sa = a.x*a.x + a.y*a.y + a.z*a.z + a.w*a.w;
    float sb = b.x*b.x + b.y*b.y + b.z*b.z + b.w*b.w;
    float dp = a.x*b.x + a.y*b.y + a.z*b.z + a.w*b.w;
    #pragma unroll
    for (int o = 16; o; o >>= 1) {
        sa += __shfl_xor_sync(0xffffffffu, sa, o);
        sb += __shfl_xor_sync(0xffffffffu, sb, o);
        dp += __shfl_xor_sync(0xffffffffu, dp, o);
    }
    float ia = 1.0f / fmaxf(sqrtf(sa), 1e-8f);
    float ib = 1.0f / fmaxf(sqrtf(sb), 1e-8f);
    if (lane == 0) {
        float pos = dp * ia * ib;
        g_pos[p] = pos;
        g_pos[p + NROWS] = pos;
    }
    float fa = ia * PSC, fb = ib * PSC;
    __half ha[4], hb[4];
    ha[0] = __float2half(a.x*fa); ha[1] = __float2half(a.y*fa);
    ha[2] = __float2half(a.z*fa); ha[3] = __float2half(a.w*fa);
    hb[0] = __float2half(b.x*fb); hb[1] = __float2half(b.y*fb);
    hb[2] = __float2half(b.z*fb); hb[3] = __float2half(b.w*fb);
    *(uint2*)(g_h + (size_t)p * D + lane * 4)           = *(uint2*)ha;
    *(uint2*)(g_h + (size_t)(p + NROWS) * D + lane * 4) = *(uint2*)hb;
}

// ---------------- tile loaders (XOR-swizzled 16B chunks, 256B rows), 128 thr ----
__device__ __forceinline__ void load_B_async(uint32_t sb, int rowBase, int t) {
    #pragma unroll
    for (int rep = 0; rep < 16; rep++) {
        int idx = rep * CTA_T + t;        // 0..2047
        int row = idx >> 4, ch = idx & 15;
        uint32_t so = SM_B + (uint32_t)(row * 256) + ((uint32_t)(ch ^ (row & 7)) << 4);
        CP_ASYNC16(sb + so, g_h + (size_t)(rowBase + row) * D + ch * 8);
    }
}
__device__ __forceinline__ void load_A_plain(char* sm, int rowBase, int t) {
    #pragma unroll
    for (int rep = 0; rep < 16; rep++) {
        int idx = rep * CTA_T + t;
        int row = idx >> 4, ch = idx & 15;
        uint32_t so = (uint32_t)(row * 256) + ((uint32_t)(ch ^ (row & 7)) << 4);
        *(uint4*)(sm + SM_A + so) = *(const uint4*)(g_h + (size_t)(rowBase + row) * D + ch * 8);
    }
}

// ---------------------------------------------------------------------------
// tile body: 64x64 warp tile (mt 4 x nt 8), f16 accumulate
// ---------------------------------------------------------------------------
__device__ __forceinline__ void tile_body(
    uint32_t (&d)[4][8][2], uint32_t bBase,
    const uint32_t (&aRow)[4], const uint32_t (&bRow)[4],
    int c4A, int c4B, int r7)
{
    #pragma unroll
    for (int mt = 0; mt < 4; mt++)
        #pragma unroll
        for (int nt = 0; nt < 8; nt++) { d[mt][nt][0] = NEG_C2; d[mt][nt][1] = NEG_C2; }

    #pragma unroll
    for (int ks = 0; ks < 8; ks++) {
        uint32_t ah[4][4], bh[16];
        const uint32_t offA = (uint32_t)(((2 * ks + c4A) ^ r7) << 4);
        const uint32_t offB = (uint32_t)(((2 * ks + c4B) ^ r7) << 4);
        #pragma unroll
        for (int mt = 0; mt < 4; mt++) ldsm4(ah[mt], aRow[mt] + offA);
        #pragma unroll
        for (int g = 0; g < 4; g++) ldsm4(bh + g * 4, bBase + bRow[g] + offB);
        #pragma unroll
        for (int mt = 0; mt < 4; mt++)
            #pragma unroll
            for (int nt = 0; nt < 8; nt++)
                mma_h(d[mt][nt], ah[mt], bh[nt * 2], bh[nt * 2 + 1]);
    }
}

// epilogue: ex2 + exact-diag substitute + row/col trees -> red[par]
__device__ __forceinline__ void epi_reduce(
    char* sm, uint32_t (&d)[4][8][2], int par, int Ie, int Je,
    int lane, int warpM, int warpN, int rq, int cq, uint32_t DIAG_H16)
{
    #pragma unroll
    for (int mt = 0; mt < 4; mt++)
        #pragma unroll
        for (int nt = 0; nt < 8; nt++) {
            ex2_h2_ip(d[mt][nt][0]);
            ex2_h2_ip(d[mt][nt][1]);
        }
    if (Ie == Je) {
        #pragma unroll
        for (int mt = 0; mt < 4; mt++) {
            #pragma unroll
            for (int q = 0; q < 2; q++) {
                const int r = warpM * 64 + mt * 16 + q * 8 + rq;
                #pragma unroll
                for (int nt = 0; nt < 8; nt++) {
                    const int c0 = warpN * 64 + nt * 8 + cq;
                    if (r == c0)     d[mt][nt][q] = (d[mt][nt][q] & 0xFFFF0000u) | DIAG_H16;
                    if (r == c0 + 1) d[mt][nt][q] = (d[mt][nt][q] & 0x0000FFFFu) | (DIAG_H16 << 16);
                }
            }
        }
    }
    float* rowred = (float*)(sm + SM_RED(par));            // [128][2]
    float* colred = (float*)(sm + SM_RED(par) + 1024);     // [128][2]
    #pragma unroll
    for (int mt = 0; mt < 4; mt++) {
        #pragma unroll
        for (int q = 0; q < 2; q++) {
            uint32_t p0 = hadd2(d[mt][0][q], d[mt][1][q]);
            uint32_t p1 = hadd2(d[mt][2][q], d[mt][3][q]);
            uint32_t p2 = hadd2(d[mt][4][q], d[mt][5][q]);
            uint32_t p3 = hadd2(d[mt][6][q], d[mt][7][q]);
            uint32_t rp = hadd2(hadd2(p0, p1), hadd2(p2, p3));
            float v = h2_low(rp) + h2_high(rp);
            v += __shfl_xor_sync(0xffffffffu, v, 1);
            v += __shfl_xor_sync(0xffffffffu, v, 2);
            if ((lane & 3) == 0) {
                int r = warpM * 64 + mt * 16 + q * 8 + rq;
                rowred[r * 2 + warpN] = v;
            }
        }
    }
    #pragma unroll
    for (int nt = 0; nt < 8; nt++) {
        uint32_t cp = hadd2(hadd2(hadd2(d[0][nt][0], d[0][nt][1]),
                                  hadd2(d[1][nt][0], d[1][nt][1])),
                            hadd2(hadd2(d[2][nt][0], d[2][nt][1]),
                                  hadd2(d[3][nt][0], d[3][nt][1])));
        cp = hadd2(cp, (uint32_t)__shfl_xor_sync(0xffffffffu, (int)cp, 4));
        cp = hadd2(cp, (uint32_t)__shfl_xor_sync(0xffffffffu, (int)cp, 8));
        cp = hadd2(cp, (uint32_t)__shfl_xor_sync(0xffffffffu, (int)cp, 16));
        if (lane < 4) {
            int c0 = warpN * 64 + nt * 8 + (lane & 3) * 2;
            colred[c0 * 2 + warpM]       = h2_low(cp);
            colred[(c0 + 1) * 2 + warpM] = h2_high(cp);
        }
    }
}
__device__ __forceinline__ void epi_write(char* sm, int par, int Ie, int Je, int t) {
    float* rowred = (float*)(sm + SM_RED(par));
    float* colred = (float*)(sm + SM_RED(par) + 1024);
    float s = rowred[t * 2] + rowred[t * 2 + 1];
    g_part[((size_t)(Ie * 128 + t)) * 64 + Je] = s;
    if (Je > Ie) {
        float c = colred[t * 2] + colred[t * 2 + 1];
        g_part[((size_t)(Je * 128 + t)) * 64 + Ie] = c;
    }
}

// ---------------------------------------------------------------------------
// Kernel 2: triangle sim-GEMM; 444 CTAs x 128 threads (3 CTAs/SM).
// Single-buffered B: per-CTA load exposure hidden by the other two CTAs.
// ---------------------------------------------------------------------------
__global__ __launch_bounds__(CTA_T, 3)
void k_main() {
    extern __shared__ char sm[];
    const uint32_t sb = smem_u32(sm);
    const int t = threadIdx.x, lane = t & 31, wid = t >> 5;
    const int warpM = wid >> 1, warpN = wid & 1;   // 2 x 2 warp grid

    const __half diag_h = __float2half(DIAG_F);
    const uint32_t DIAG_H16 = (uint32_t)*(const uint16_t*)&diag_h;

    const int jb = (int)(((long)blockIdx.x * NJOBS) / GRID_MAIN);
    const int je = (int)(((long)(blockIdx.x + 1) * NJOBS) / GRID_MAIN);
    const int njobs = je - jb;

    const int r7   = lane & 7;
    const int rowA = (lane & 7) + ((lane >> 3) & 1) * 8;  const int c4A = lane >> 4;
    const int rowB = (lane & 7) + ((lane >> 4) << 3);     const int c4B = (lane >> 3) & 1;
    const int rq = lane >> 2;
    const int cq = (lane & 3) * 2;

    uint32_t aRow[4];
    #pragma unroll
    for (int mt = 0; mt < 4; mt++)
        aRow[mt] = sb + SM_A + (uint32_t)((warpM * 64 + mt * 16 + rowA) * 256);
    uint32_t bRow[4];
    #pragma unroll
    for (int g = 0; g < 4; g++)
        bRow[g] = (uint32_t)((warpN * 64 + g * 16 + rowB) * 256);

    uint32_t d[4][8][2];

    int Ic, Jc; job_ij(jb, Ic, Jc);
    int Ia = -1, prevI = 0, prevJ = 0;

    // prologue: B for job 0
    load_B_async(sb, Jc * 128, t); CP_COMMIT();

    for (int jj = 0; jj < njobs; jj++) {
        CP_WAIT0();
        __syncthreads();                         // B ready; red[(jj-1)&1] complete
        if (jj > 0) epi_write(sm, (jj - 1) & 1, prevI, prevJ, t);
        if (Ic != Ia) { load_A_plain(sm, Ic * 128, t); __syncthreads(); Ia = Ic; }
        tile_body(d, sb + SM_B, aRow, bRow, c4A, c4B, r7);
        __syncthreads();                         // all warps done reading B
        if (jj + 1 < njobs) {
            int In = Ic, Jn = Jc; job_adv(In, Jn);
            load_B_async(sb, Jn * 128, t);
        }
        CP_COMMIT();
        epi_reduce(sm, d, jj & 1, Ic, Jc, lane, warpM, warpN, rq, cq, DIAG_H16);
        prevI = Ic; prevJ = Jc; job_adv(Ic, Jc);
    }
    __syncthreads();
    epi_write(sm, (njobs - 1) & 1, prevI, prevJ, t);
}

// ---------------------------------------------------------------------------
// Kernel 3: per-row loss (coalesced float4 reads) + reduction.
// ---------------------------------------------------------------------------
__global__ void k_tail(float* __restrict__ out) {
    __shared__ float red[256];
    __shared__ bool isLast;
    int r = blockIdx.x * 256 + threadIdx.x;
    const float4* base = (const float4*)(g_part + (size_t)r * 64);
    float S = 0.0f;
    #pragma unroll
    for (int q = 0; q < 16; q++) {
        float4 v = base[q];
        S += v.x + v.y + v.z + v.w;
    }
    float p = g_pos[r];
    float Sf = S + expf(fmaf(10.0f, p, -TAIL_C));
    red[threadIdx.x] = logf(Sf) + TAIL_C - 10.0f * p;
    __syncthreads();
    for (int s = 128; s; s >>= 1) {
        if (threadIdx.x < s) red[threadIdx.x] += red[threadIdx.x + s];
        __syncthreads();
    }
    if (threadIdx.x == 0) {
        g_bsum[blockIdx.x] = red[0];
        __threadfence();
        unsigned int done = atomicAdd(&g_cnt, 1u);
        isLast = (done == 31u);
    }
    __syncthreads();
    if (isLast && threadIdx.x == 0) {
        float acc = 0.0f;
        #pragma unroll
        for (int b = 0; b < 32; b++) acc += ((volatile float*)g_bsum)[b];
        out[0] = acc * (1.0f / (float)TWO_N);
        g_cnt = 0;
    }
}

// ---------------------------------------------------------------------------
extern "C" void kernel_launch(void* const* d_in, const int* in_sizes, int n_in,
                              void* d_out, int out_size) {
    const float* zi = (const float*)d_in[0];
    const float* zj = (const float*)d_in[1];
    float* out = (float*)d_out;

    cudaFuncSetAttribute(k_main, cudaFuncAttributeMaxDynamicSharedMemorySize, SMEM_BYTES);

    k_prep<<<512, 256>>>(zi, zj);
    k_main<<<GRID_MAIN, CTA_T, SMEM_BYTES>>>();
    k_tail<<<32, 256>>>(out);
}